// round 1
// baseline (speedup 1.0000x reference)
#include <cuda_runtime.h>

// ---------------------------------------------------------------------------
// DecoderBlock: conv3x3(64->3) + bias + tanh  -> ll [16,3,128,128]
// then two inverse Haar levels (fused):       -> out [16,3,512,512]
//
// Inputs (metadata order):
//   d_in[0] fused  f32 [16,64,128,128]
//   d_in[1] hf1    f32 [16,9,256,256]
//   d_in[2] hf2    f32 [16,9,128,128]
//   d_in[3] conv_w f32 [3,64,3,3]
//   d_in[4] conv_b f32 [3]
// Output: f32 [16,3,512,512]
// ---------------------------------------------------------------------------

#define NB   16
#define CIN  64
#define HH   128
#define WW   128

// intermediate ll (conv output after tanh): 16*3*128*128 floats = 3 MB
__device__ float g_ll[NB * 3 * HH * WW];

// ---------------------------------------------------------------------------
// Kernel A: tiled conv 3x3 pad 1, 64->3 channels, + bias + tanh
// Tile: 64(w) x 32(h) outputs per CTA, 256 threads = (16,16),
// each thread computes a 2(row) x 4(col) block for all 3 output channels.
// Input channels processed in chunks of 4 through shared memory.
// ---------------------------------------------------------------------------
#define CCHUNK 4
#define SH_Y   34          // 32 + 2 halo
#define SH_X   66          // 64 + 2 halo
#define SH_PLANE (SH_Y * SH_X)   // 2244

__global__ __launch_bounds__(256) void conv_tanh_kernel(
    const float* __restrict__ fused,
    const float* __restrict__ conv_w,
    const float* __restrict__ conv_b)
{
    __shared__ float s_in[CCHUNK * SH_PLANE];   // 35904 B
    __shared__ float s_w[CIN * 27];             // 6912 B, layout [c][o][9]

    const int tid    = threadIdx.y * 16 + threadIdx.x;
    const int b      = blockIdx.z;
    const int base_x = blockIdx.x * 64;
    const int base_y = blockIdx.y * 32;

    // stage all weights to shared, channel-major: s_w[c*27 + o*9 + t]
    for (int i = tid; i < CIN * 27; i += 256) {
        int c = i / 27, rem = i % 27;
        int o = rem / 9, t = rem % 9;
        s_w[i] = conv_w[o * (CIN * 9) + c * 9 + t];
    }

    float acc[3][2][4];
#pragma unroll
    for (int o = 0; o < 3; o++)
#pragma unroll
        for (int p = 0; p < 2; p++)
#pragma unroll
            for (int q = 0; q < 4; q++) acc[o][p][q] = 0.0f;

    const int lx0 = threadIdx.x * 4;   // local out col base (0..60)
    const int ly0 = threadIdx.y * 2;   // local out row base (0..30)

    for (int cc0 = 0; cc0 < CIN; cc0 += CCHUNK) {
        __syncthreads();
        // load CCHUNK input planes (with halo) into shared
        for (int i = tid; i < CCHUNK * SH_PLANE; i += 256) {
            int c   = i / SH_PLANE;
            int rem = i - c * SH_PLANE;
            int r   = rem / SH_X;
            int col = rem - r * SH_X;
            int gh  = base_y + r - 1;
            int gw  = base_x + col - 1;
            float v = 0.0f;
            if (gh >= 0 && gh < HH && gw >= 0 && gw < WW)
                v = fused[((b * CIN + cc0 + c) * HH + gh) * WW + gw];
            s_in[i] = v;
        }
        __syncthreads();

#pragma unroll
        for (int c = 0; c < CCHUNK; c++) {
            // 4 rows x 6 cols of inputs covering the 2x4 output block + halo
            float xv[4][6];
            const float* sp = &s_in[c * SH_PLANE];
#pragma unroll
            for (int rr = 0; rr < 4; rr++)
#pragma unroll
                for (int cx = 0; cx < 6; cx++)
                    xv[rr][cx] = sp[(ly0 + rr) * SH_X + lx0 + cx];

            const float* wp = &s_w[(cc0 + c) * 27];
#pragma unroll
            for (int o = 0; o < 3; o++) {
                float wv[9];
#pragma unroll
                for (int t = 0; t < 9; t++) wv[t] = wp[o * 9 + t];
#pragma unroll
                for (int dy = 0; dy < 3; dy++)
#pragma unroll
                    for (int dx = 0; dx < 3; dx++)
#pragma unroll
                        for (int p = 0; p < 2; p++)
#pragma unroll
                            for (int q = 0; q < 4; q++)
                                acc[o][p][q] += wv[dy * 3 + dx] * xv[p + dy][q + dx];
            }
        }
    }

    // bias + tanh + vectorized store of the 2x4 block per out channel
#pragma unroll
    for (int o = 0; o < 3; o++) {
        const float bias = conv_b[o];
#pragma unroll
        for (int p = 0; p < 2; p++) {
            float4 v;
            v.x = tanhf(acc[o][p][0] + bias);
            v.y = tanhf(acc[o][p][1] + bias);
            v.z = tanhf(acc[o][p][2] + bias);
            v.w = tanhf(acc[o][p][3] + bias);
            const int gy = base_y + ly0 + p;
            const int gx = base_x + lx0;
            *reinterpret_cast<float4*>(
                &g_ll[((b * 3 + o) * HH + gy) * WW + gx]) = v;
        }
    }
}

// ---------------------------------------------------------------------------
// Kernel B: fused double inverse Haar.
// One thread per coarse ll pixel (b,c,h0,w0):
//   level 1: 2x2 butterfly with hf2 -> cur[2][2] (256-scale values)
//   level 2: each cur value + 3 hf1 values -> 2x2 output -> 4x4 block total
// Haar butterfly (a=LL, b=LH, c=HL, d=HH, hf scaled 2x-1):
//   out00=.5(a-b-c+d) out01=.5(a-b+c-d) out10=.5(a+b-c-d) out11=.5(a+b+c+d)
// ---------------------------------------------------------------------------
__global__ __launch_bounds__(256) void iwt2_kernel(
    const float* __restrict__ hf1,
    const float* __restrict__ hf2,
    float* __restrict__ out)
{
    const int w0 = threadIdx.x;                        // 0..127
    const int h0 = blockIdx.x * 2 + threadIdx.y;       // 0..127
    const int z  = blockIdx.y;                         // b*3 + c
    const int b  = z / 3;
    const int c  = z - b * 3;

    const float a = g_ll[(z * HH + h0) * WW + w0];

    // level-1 hf2 (128x128 planes)
    const int hf2base = ((b * 9 + 3 * c) * HH + h0) * WW + w0;
    const float lh = 2.0f * __ldg(&hf2[hf2base            ]) - 1.0f;
    const float hl = 2.0f * __ldg(&hf2[hf2base + HH * WW  ]) - 1.0f;
    const float hh = 2.0f * __ldg(&hf2[hf2base + 2*HH*WW  ]) - 1.0f;

    float cur[2][2];
    cur[0][0] = 0.5f * (a - lh - hl + hh);
    cur[0][1] = 0.5f * (a - lh + hl - hh);
    cur[1][0] = 0.5f * (a + lh - hl - hh);
    cur[1][1] = 0.5f * (a + lh + hl + hh);

    // level-2 hf1 (256x256 planes): 3 channels x 2 rows, float2 along cols
    const int h1 = 2 * h0;
    const int w1 = 2 * w0;
    float2 v[3][2];
#pragma unroll
    for (int k = 0; k < 3; k++) {
#pragma unroll
        for (int p0 = 0; p0 < 2; p0++) {
            const float2* ptr = reinterpret_cast<const float2*>(
                &hf1[((b * 9 + 3 * c + k) * 256 + (h1 + p0)) * 256 + w1]);
            v[k][p0] = __ldg(ptr);
        }
    }

    float o16[4][4];
#pragma unroll
    for (int p0 = 0; p0 < 2; p0++) {
#pragma unroll
        for (int q0 = 0; q0 < 2; q0++) {
            const float a2  = cur[p0][q0];
            const float lh1 = 2.0f * (q0 == 0 ? v[0][p0].x : v[0][p0].y) - 1.0f;
            const float hl1 = 2.0f * (q0 == 0 ? v[1][p0].x : v[1][p0].y) - 1.0f;
            const float hh1 = 2.0f * (q0 == 0 ? v[2][p0].x : v[2][p0].y) - 1.0f;
            o16[2 * p0 + 0][2 * q0 + 0] = 0.5f * (a2 - lh1 - hl1 + hh1);
            o16[2 * p0 + 0][2 * q0 + 1] = 0.5f * (a2 - lh1 + hl1 - hh1);
            o16[2 * p0 + 1][2 * q0 + 0] = 0.5f * (a2 + lh1 - hl1 - hh1);
            o16[2 * p0 + 1][2 * q0 + 1] = 0.5f * (a2 + lh1 + hl1 + hh1);
        }
    }

    // write 4x4 block as 4 float4 rows (coalesced across w0)
#pragma unroll
    for (int r = 0; r < 4; r++) {
        float4 row;
        row.x = o16[r][0]; row.y = o16[r][1];
        row.z = o16[r][2]; row.w = o16[r][3];
        *reinterpret_cast<float4*>(
            &out[((long)z * 512 + (4 * h0 + r)) * 512 + 4 * w0]) = row;
    }
}

// ---------------------------------------------------------------------------
extern "C" void kernel_launch(void* const* d_in, const int* in_sizes, int n_in,
                              void* d_out, int out_size)
{
    const float* fused  = (const float*)d_in[0];
    const float* hf1    = (const float*)d_in[1];
    const float* hf2    = (const float*)d_in[2];
    const float* conv_w = (const float*)d_in[3];
    const float* conv_b = (const float*)d_in[4];
    float* out = (float*)d_out;

    dim3 cb(16, 16);
    dim3 cg(WW / 64, HH / 32, NB);          // (2,4,16) = 128 CTAs
    conv_tanh_kernel<<<cg, cb>>>(fused, conv_w, conv_b);

    dim3 ib(128, 2);
    dim3 ig(HH / 2, NB * 3);                // (64,48) = 3072 CTAs
    iwt2_kernel<<<ig, ib>>>(hf1, hf2, out);
}